// round 7
// baseline (speedup 1.0000x reference)
#include <cuda_runtime.h>
#include <cstdint>
#include <cstddef>

// ---------------- problem constants ----------------
static constexpr int E_EDGES = 131072;
static constexpr int T_TRIP  = 1048576;
static constexpr int H_DIM   = 256;
static constexpr int I_DIM   = 64;
static constexpr int NR      = 6;
static constexpr int NSR     = 42;
static constexpr int BAS     = 8;

// ---------------- scratch (static device memory) ----------------
__device__ float g_xr  [(size_t)E_EDGES * H_DIM];
__device__ float g_xji [(size_t)E_EDGES * H_DIM];
__device__ float g_bufA[(size_t)E_EDGES * H_DIM];
__device__ float g_bufB[(size_t)E_EDGES * H_DIM];
__device__ float g_xkjd[(size_t)E_EDGES * I_DIM];
__device__ float g_agg [(size_t)E_EDGES * I_DIM];
__device__ float g_wr  [622592];   // tf32-rounded weights, concatenated

// weight offsets inside g_wr
static constexpr int WO_JI   = 0;
static constexpr int WO_KJ   = 65536;
static constexpr int WO_B11  = 131072;
static constexpr int WO_B12  = 196608;
static constexpr int WO_LIN  = 262144;
static constexpr int WO_A11  = 327680;
static constexpr int WO_A12  = 393216;
static constexpr int WO_A21  = 458752;
static constexpr int WO_A22  = 524288;
static constexpr int WO_DOWN = 589824;   // 256*64
static constexpr int WO_UP   = 606208;   // 64*256

// ---------------- helpers ----------------
__device__ __forceinline__ uint32_t smem_to_u32(const void* p) {
    uint32_t a;
    asm("{ .reg .u64 t; cvta.to.shared.u64 t, %1; cvt.u32.u64 %0, t; }" : "=r"(a) : "l"(p));
    return a;
}
__device__ __forceinline__ uint32_t tf32r(float v) {
    uint32_t o; asm("cvt.rna.tf32.f32 %0, %1;" : "=r"(o) : "f"(v)); return o;
}
__device__ __forceinline__ float silu_f(float v) {
    return v * (1.0f / (1.0f + __expf(-v)));
}
__device__ __forceinline__ void cp_async16(uint32_t dst, const void* src) {
    asm volatile("cp.async.cg.shared.global [%0], [%1], 16;" :: "r"(dst), "l"(src));
}
__device__ __forceinline__ void mma_tf32(float d[4], const uint32_t a[4], const uint32_t b[2]) {
    asm volatile(
        "mma.sync.aligned.m16n8k8.row.col.f32.tf32.tf32.f32 "
        "{%0,%1,%2,%3}, {%4,%5,%6,%7}, {%8,%9}, {%0,%1,%2,%3};"
        : "+f"(d[0]), "+f"(d[1]), "+f"(d[2]), "+f"(d[3])
        : "r"(a[0]), "r"(a[1]), "r"(a[2]), "r"(a[3]), "r"(b[0]), "r"(b[1]));
}

// ============ full-width tf32 GEMM: C[:,0:256] = [res +] silu(A @ W [+ bias]) ============
// Block tile: 128 x 256 x 16. 8 warps as 2(M) x 4(N); warp tile 64 x 64.
// A read exactly once from DRAM. LDS:MMA = 1.0 in the inner loop.
template <int K, int ROUND_OUT>
__global__ void __launch_bounds__(256, 1)
gemm_fw(const float* __restrict__ A, const float* __restrict__ W,
        const float* __restrict__ bias, const float* __restrict__ res,
        float* __restrict__ C)
{
    constexpr int BM = 128, BN = 256, BK = 16;
    constexpr int KT = K / BK;
    constexpr int DEPTH = (KT >= 4) ? 4 : 3;
    constexpr int AS = BK + 4;            // 20
    constexpr int WS = BN + 4;            // 260
    constexpr int A_STAGE = BM * AS;      // 2560 floats
    constexpr int W_STAGE = BK * WS;      // 4160 floats

    extern __shared__ float sm[];
    float* As = sm;
    float* Ws = sm + DEPTH * A_STAGE;
    const uint32_t uAs = smem_to_u32(As);
    const uint32_t uWs = smem_to_u32(Ws);

    const int tid = threadIdx.x, lane = tid & 31, wid = tid >> 5;
    const int warpM = wid >> 2, warpN = wid & 3;     // 2 x 4
    const int g = lane >> 2, q = lane & 3;
    const int row0 = blockIdx.x * BM;

    float acc[4][8][4];
#pragma unroll
    for (int mf = 0; mf < 4; mf++)
#pragma unroll
        for (int nf = 0; nf < 8; nf++)
#pragma unroll
            for (int v = 0; v < 4; v++) acc[mf][nf][v] = 0.0f;

    auto load_stage = [&](int s, int kt) {
        const int k0 = kt * BK;
        // A: 128 x 16 = 512 float4 chunks, 2 per thread
#pragma unroll
        for (int i = 0; i < 2; i++) {
            int id = tid + i * 256;
            int m = id >> 2, c4 = (id & 3) * 4;
            cp_async16(uAs + (uint32_t)(s * A_STAGE + m * AS + c4) * 4,
                       A + (size_t)(row0 + m) * K + k0 + c4);
        }
        // W: 16 x 256 = 1024 float4 chunks, 4 per thread
#pragma unroll
        for (int i = 0; i < 4; i++) {
            int id = tid + i * 256;
            int k = id >> 6, n4 = (id & 63) * 4;
            cp_async16(uWs + (uint32_t)(s * W_STAGE + k * WS + n4) * 4,
                       W + (size_t)(k0 + k) * BN + n4);
        }
    };

#pragma unroll
    for (int s = 0; s < DEPTH - 1; s++) {
        load_stage(s, s);
        asm volatile("cp.async.commit_group;" ::: "memory");
    }

    for (int it = 0; it < KT; it++) {
        asm volatile("cp.async.wait_group %0;" :: "n"(DEPTH - 2) : "memory");
        __syncthreads();
        const int nx = it + DEPTH - 1;
        if (nx < KT) load_stage(nx % DEPTH, nx);
        asm volatile("cp.async.commit_group;" ::: "memory");

        const int s = it % DEPTH;
        const float* Asb = As + s * A_STAGE;
        const float* Wsb = Ws + s * W_STAGE;
#pragma unroll
        for (int ks = 0; ks < 2; ks++) {
            uint32_t af[4][4];
#pragma unroll
            for (int mf = 0; mf < 4; mf++) {
                int r = warpM * 64 + mf * 16 + g;
                af[mf][0] = __float_as_uint(Asb[r * AS + ks * 8 + q]);
                af[mf][1] = __float_as_uint(Asb[(r + 8) * AS + ks * 8 + q]);
                af[mf][2] = __float_as_uint(Asb[r * AS + ks * 8 + q + 4]);
                af[mf][3] = __float_as_uint(Asb[(r + 8) * AS + ks * 8 + q + 4]);
            }
            uint32_t bf[8][2];
#pragma unroll
            for (int nf = 0; nf < 8; nf++) {
                int c = warpN * 64 + nf * 8 + g;
                bf[nf][0] = __float_as_uint(Wsb[(ks * 8 + q) * WS + c]);
                bf[nf][1] = __float_as_uint(Wsb[(ks * 8 + q + 4) * WS + c]);
            }
#pragma unroll
            for (int mf = 0; mf < 4; mf++)
#pragma unroll
                for (int nf = 0; nf < 8; nf++)
                    mma_tf32(acc[mf][nf], af[mf], bf[nf]);
        }
    }
    asm volatile("cp.async.wait_group 0;" ::: "memory");

    // epilogue: bias -> silu -> +res -> store (tf32-rounded unless final)
#pragma unroll
    for (int mf = 0; mf < 4; mf++) {
#pragma unroll
        for (int nf = 0; nf < 8; nf++) {
            const int col = warpN * 64 + nf * 8 + 2 * q;
            float bv0 = 0.0f, bv1 = 0.0f;
            if (bias) { bv0 = bias[col]; bv1 = bias[col + 1]; }
#pragma unroll
            for (int h = 0; h < 2; h++) {
                const int row = row0 + warpM * 64 + mf * 16 + g + h * 8;
                float v0 = silu_f(acc[mf][nf][h * 2 + 0] + bv0);
                float v1 = silu_f(acc[mf][nf][h * 2 + 1] + bv1);
                const size_t off = (size_t)row * BN + col;
                if (res) {
                    float2 r = *reinterpret_cast<const float2*>(res + off);
                    v0 += r.x; v1 += r.y;
                }
                uint2 o;
                o.x = ROUND_OUT ? tf32r(v0) : __float_as_uint(v0);
                o.y = ROUND_OUT ? tf32r(v1) : __float_as_uint(v1);
                *reinterpret_cast<uint2*>(C + off) = o;
            }
        }
    }
}

static constexpr int fw_smem(int K) {
    int depth = (K / 16 >= 4) ? 4 : 3;
    return depth * (128 * 20 + 16 * 260) * 4;
}

// ============ narrow GEMM (proven R5): C[:,0:64] = silu(A @ W) ============
template <int BN, int K>
__global__ void __launch_bounds__(256, 2)
mma_gemm(const float* __restrict__ A, const float* __restrict__ W,
         const float* __restrict__ bias, const float* __restrict__ res,
         float* __restrict__ C, int Nfull)
{
    constexpr int BM = 128, BK = 16, DEPTH = 3;
    constexpr int KT = K / BK;
    constexpr int AS_STRIDE = BK + 4;
    constexpr int AS_STAGE  = BM * AS_STRIDE;
    constexpr int BS_STRIDE = BN + 4;
    constexpr int BS_STAGE  = BK * BS_STRIDE;
    constexpr int NF = BN / 16;

    extern __shared__ float smf[];
    float* As = smf;
    float* Bs = smf + DEPTH * AS_STAGE;
    const uint32_t smemA = smem_to_u32(As);
    const uint32_t smemB = smem_to_u32(Bs);

    const int tid = threadIdx.x, lane = tid & 31, wid = tid >> 5;
    const int warpM = wid >> 1, warpN = wid & 1;
    const int row0 = blockIdx.x * BM;
    const int col0 = blockIdx.y * BN;
    const int g = lane >> 2, q = lane & 3;

    float acc[2][NF][4];
#pragma unroll
    for (int mf = 0; mf < 2; mf++)
#pragma unroll
        for (int nf = 0; nf < NF; nf++)
#pragma unroll
            for (int v = 0; v < 4; v++) acc[mf][nf][v] = 0.0f;

    auto load_stage = [&](int s, int kt) {
        const int k0 = kt * BK;
#pragma unroll
        for (int i = 0; i < 2; i++) {
            int id = tid + i * 256;
            int m = id >> 2, c4 = (id & 3) * 4;
            cp_async16(smemA + (uint32_t)(s * AS_STAGE + m * AS_STRIDE + c4) * 4,
                       A + (size_t)(row0 + m) * K + k0 + c4);
        }
        constexpr int BCH = BK * BN / 4;
#pragma unroll
        for (int i = 0; i < (BCH + 255) / 256; i++) {
            int id = tid + i * 256;
            if (id < BCH) {
                int k = id / (BN / 4), n4 = (id % (BN / 4)) * 4;
                cp_async16(smemB + (uint32_t)(s * BS_STAGE + k * BS_STRIDE + n4) * 4,
                           W + (size_t)(k0 + k) * Nfull + col0 + n4);
            }
        }
    };

#pragma unroll
    for (int s = 0; s < DEPTH - 1; s++) {
        load_stage(s, s);
        asm volatile("cp.async.commit_group;" ::: "memory");
    }

    for (int it = 0; it < KT; it++) {
        asm volatile("cp.async.wait_group %0;" :: "n"(DEPTH - 2) : "memory");
        __syncthreads();
        const int nx = it + DEPTH - 1;
        if (nx < KT) load_stage(nx % DEPTH, nx);
        asm volatile("cp.async.commit_group;" ::: "memory");

        const int s = it % DEPTH;
        const float* Asb = As + s * AS_STAGE;
        const float* Bsb = Bs + s * BS_STAGE;
#pragma unroll
        for (int ks = 0; ks < 2; ks++) {
            uint32_t af[2][4];
            uint32_t bf[NF][2];
#pragma unroll
            for (int mf = 0; mf < 2; mf++) {
                int r = warpM * 32 + mf * 16 + g;
                af[mf][0] = __float_as_uint(Asb[r * AS_STRIDE + ks * 8 + q]);
                af[mf][1] = __float_as_uint(Asb[(r + 8) * AS_STRIDE + ks * 8 + q]);
                af[mf][2] = __float_as_uint(Asb[r * AS_STRIDE + ks * 8 + q + 4]);
                af[mf][3] = __float_as_uint(Asb[(r + 8) * AS_STRIDE + ks * 8 + q + 4]);
            }
#pragma unroll
            for (int nf = 0; nf < NF; nf++) {
                int c = warpN * (BN / 2) + nf * 8 + g;
                bf[nf][0] = __float_as_uint(Bsb[(ks * 8 + q) * BS_STRIDE + c]);
                bf[nf][1] = __float_as_uint(Bsb[(ks * 8 + q + 4) * BS_STRIDE + c]);
            }
#pragma unroll
            for (int mf = 0; mf < 2; mf++)
#pragma unroll
                for (int nf = 0; nf < NF; nf++)
                    mma_tf32(acc[mf][nf], af[mf], bf[nf]);
        }
    }

#pragma unroll
    for (int mf = 0; mf < 2; mf++) {
#pragma unroll
        for (int nf = 0; nf < NF; nf++) {
            const int col = col0 + warpN * (BN / 2) + nf * 8 + 2 * q;
            float bv0 = 0.0f, bv1 = 0.0f;
            if (bias) { bv0 = bias[col]; bv1 = bias[col + 1]; }
#pragma unroll
            for (int h = 0; h < 2; h++) {
                const int row = row0 + warpM * 32 + mf * 16 + g + h * 8;
                float v0 = silu_f(acc[mf][nf][h * 2 + 0] + bv0);
                float v1 = silu_f(acc[mf][nf][h * 2 + 1] + bv1);
                const size_t off = (size_t)row * Nfull + col;
                if (res) {
                    float2 r = *reinterpret_cast<const float2*>(res + off);
                    v0 += r.x; v1 += r.y;
                }
                uint2 o;
                o.x = tf32r(v0);
                o.y = tf32r(v1);
                *reinterpret_cast<uint2*>(C + off) = o;
            }
        }
    }
}

static constexpr int mma_smem(int BN) {
    return 3 * (128 * 20 + 16 * (BN + 4)) * 4;
}

// ---------------- round x to tf32-representable fp32 ----------------
__global__ void round_copy_kernel(const float4* __restrict__ in, float4* __restrict__ out, int n4)
{
    int i = blockIdx.x * blockDim.x + threadIdx.x;
    int stride = gridDim.x * blockDim.x;
    for (; i < n4; i += stride) {
        float4 v = in[i];
        uint4 o;
        o.x = tf32r(v.x); o.y = tf32r(v.y); o.z = tf32r(v.z); o.w = tf32r(v.w);
        *reinterpret_cast<uint4*>(&out[i]) = o;
    }
}

// ---------------- round all weights, one launch ----------------
struct WSet { const float* src[11]; float* dst[11]; int n4[11]; };
__global__ void round_w_kernel(WSet ws)
{
    int seg = blockIdx.y;
    const float4* s = reinterpret_cast<const float4*>(ws.src[seg]);
    float4* d = reinterpret_cast<float4*>(ws.dst[seg]);
    int n4 = ws.n4[seg];
    for (int i = blockIdx.x * blockDim.x + threadIdx.x; i < n4; i += gridDim.x * blockDim.x) {
        float4 v = s[i];
        uint4 o;
        o.x = tf32r(v.x); o.y = tf32r(v.y); o.z = tf32r(v.z); o.w = tf32r(v.w);
        *reinterpret_cast<uint4*>(&d[i]) = o;
    }
}

// ---------------- rbf gating: xkj[r,:] *= (rbf[r,:] @ W1) @ W2 ; tf32-rounded ----------------
__global__ void rbf_gate_kernel(float* __restrict__ xkj,
                                const float* __restrict__ rbf,
                                const float* __restrict__ W1,   // [6,8]
                                const float* __restrict__ W2)   // [8,256]
{
    __shared__ __align__(16) float sW2[BAS * H_DIM];
    __shared__ float sW1[NR * BAS];
    for (int i = threadIdx.x; i < BAS * H_DIM; i += blockDim.x) sW2[i] = W2[i];
    for (int i = threadIdx.x; i < NR * BAS; i += blockDim.x)    sW1[i] = W1[i];
    __syncthreads();

    const int lane  = threadIdx.x & 31;
    const int wglob = (blockIdx.x * blockDim.x + threadIdx.x) >> 5;
    const int nwarp = (gridDim.x * blockDim.x) >> 5;
    const int j = lane & 7;
    const int g = lane >> 3;

    for (int r = wglob; r < E_EDGES; r += nwarp) {
        float s = 0.f;
        for (int i = g; i < NR; i += 4) s += rbf[(size_t)r * NR + i] * sW1[i * BAS + j];
        s += __shfl_xor_sync(0xffffffffu, s, 8);
        s += __shfl_xor_sync(0xffffffffu, s, 16);
        int c = lane * 8;
        float4 g0 = make_float4(0, 0, 0, 0), g1 = make_float4(0, 0, 0, 0);
#pragma unroll
        for (int jj = 0; jj < BAS; jj++) {
            float sj = __shfl_sync(0xffffffffu, s, jj);
            float4 w0 = *reinterpret_cast<const float4*>(&sW2[jj * H_DIM + c]);
            float4 w1 = *reinterpret_cast<const float4*>(&sW2[jj * H_DIM + c + 4]);
            g0.x += sj * w0.x; g0.y += sj * w0.y; g0.z += sj * w0.z; g0.w += sj * w0.w;
            g1.x += sj * w1.x; g1.y += sj * w1.y; g1.z += sj * w1.z; g1.w += sj * w1.w;
        }
        float4* p0 = reinterpret_cast<float4*>(&xkj[(size_t)r * H_DIM + c]);
        float4* p1 = reinterpret_cast<float4*>(&xkj[(size_t)r * H_DIM + c + 4]);
        float4 x0 = *p0, x1 = *p1;
        uint4 o0, o1;
        o0.x = tf32r(x0.x * g0.x); o0.y = tf32r(x0.y * g0.y);
        o0.z = tf32r(x0.z * g0.z); o0.w = tf32r(x0.w * g0.w);
        o1.x = tf32r(x1.x * g1.x); o1.y = tf32r(x1.y * g1.y);
        o1.z = tf32r(x1.z * g1.z); o1.w = tf32r(x1.w * g1.w);
        *reinterpret_cast<uint4*>(p0) = o0;
        *reinterpret_cast<uint4*>(p1) = o1;
    }
}

// ---------------- zero scratch ----------------
__global__ void zero_kernel(float4* __restrict__ p, int n4)
{
    int i = blockIdx.x * blockDim.x + threadIdx.x;
    int stride = gridDim.x * blockDim.x;
    for (; i < n4; i += stride) p[i] = make_float4(0, 0, 0, 0);
}

// ---------------- triplet pass ----------------
__global__ void triplet_kernel(const float* __restrict__ sbf,
                               const int* __restrict__ idx_kj,
                               const int* __restrict__ idx_ji,
                               const float* __restrict__ W1,   // [42,8]
                               const float* __restrict__ W2,   // [8,64]
                               const float* __restrict__ xkjd, // [E,64]
                               float* __restrict__ agg)        // [E,64]
{
    __shared__ float sW1[NSR * BAS];
    __shared__ __align__(16) float sW2[BAS * I_DIM];
    for (int i = threadIdx.x; i < NSR * BAS; i += blockDim.x) sW1[i] = W1[i];
    for (int i = threadIdx.x; i < BAS * I_DIM; i += blockDim.x) sW2[i] = W2[i];
    __syncthreads();

    const int lane  = threadIdx.x & 31;
    const int wglob = (blockIdx.x * blockDim.x + threadIdx.x) >> 5;
    const int nwarp = (gridDim.x * blockDim.x) >> 5;
    const int sub = lane >> 4;
    const int sl  = lane & 15;
    const int j   = sl & 7;
    const int g   = sl >> 3;

    for (int p = wglob; p * 2 < T_TRIP; p += nwarp) {
        int t = p * 2 + sub;
        const float* srow = sbf + (size_t)t * NSR;
        float s = 0.f;
        for (int i = g; i < NSR; i += 2) s += srow[i] * sW1[i * BAS + j];
        s += __shfl_xor_sync(0xffffffffu, s, 8);

        int ekj = idx_kj[t];
        int eji = idx_ji[t];
        int c = sl * 4;
        float4 xv = *reinterpret_cast<const float4*>(&xkjd[(size_t)ekj * I_DIM + c]);
        float4 m = make_float4(0, 0, 0, 0);
#pragma unroll
        for (int jj = 0; jj < BAS; jj++) {
            float sj = __shfl_sync(0xffffffffu, s, (sub << 4) + jj);
            float4 w = *reinterpret_cast<const float4*>(&sW2[jj * I_DIM + c]);
            m.x += sj * w.x; m.y += sj * w.y; m.z += sj * w.z; m.w += sj * w.w;
        }
        m.x *= xv.x; m.y *= xv.y; m.z *= xv.z; m.w *= xv.w;
        atomicAdd(reinterpret_cast<float4*>(&agg[(size_t)eji * I_DIM + c]), m);
    }
}

// ---------------- launch ----------------
extern "C" void kernel_launch(void* const* d_in, const int* in_sizes, int n_in,
                              void* d_out, int out_size)
{
    const float* x      = (const float*)d_in[0];
    const float* rbf    = (const float*)d_in[1];
    const float* sbf    = (const float*)d_in[2];
    const int*   idx_kj = (const int*)d_in[3];
    const int*   idx_ji = (const int*)d_in[4];
    const float* W_ji   = (const float*)d_in[5];
    const float* b_ji   = (const float*)d_in[6];
    const float* W_kj   = (const float*)d_in[7];
    const float* b_kj   = (const float*)d_in[8];
    const float* W_rbf1 = (const float*)d_in[9];
    const float* W_rbf2 = (const float*)d_in[10];
    const float* W_sbf1 = (const float*)d_in[11];
    const float* W_sbf2 = (const float*)d_in[12];
    const float* W_down = (const float*)d_in[13];
    const float* W_up   = (const float*)d_in[14];
    const float* Wb1_1  = (const float*)d_in[15];
    const float* bb1_1  = (const float*)d_in[16];
    const float* Wb1_2  = (const float*)d_in[17];
    const float* bb1_2  = (const float*)d_in[18];
    const float* W_lin  = (const float*)d_in[19];
    const float* b_lin  = (const float*)d_in[20];
    const float* Wa1_1  = (const float*)d_in[21];
    const float* ba1_1  = (const float*)d_in[22];
    const float* Wa1_2  = (const float*)d_in[23];
    const float* ba1_2  = (const float*)d_in[24];
    const float* Wa2_1  = (const float*)d_in[25];
    const float* ba2_1  = (const float*)d_in[26];
    const float* Wa2_2  = (const float*)d_in[27];
    const float* ba2_2  = (const float*)d_in[28];
    float* out = (float*)d_out;

    float *xr, *xji, *bufA, *bufB, *xkjd, *agg, *wr;
    cudaGetSymbolAddress((void**)&xr,   g_xr);
    cudaGetSymbolAddress((void**)&xji,  g_xji);
    cudaGetSymbolAddress((void**)&bufA, g_bufA);
    cudaGetSymbolAddress((void**)&bufB, g_bufB);
    cudaGetSymbolAddress((void**)&xkjd, g_xkjd);
    cudaGetSymbolAddress((void**)&agg,  g_agg);
    cudaGetSymbolAddress((void**)&wr,   g_wr);

    constexpr int SM_FW256 = fw_smem(256);   // DEPTH=4, ~105 KB
    constexpr int SM_FW64  = fw_smem(64);    // K=64 -> KT=4 -> DEPTH=4
    constexpr int SM_DOWN  = mma_smem(64);
    cudaFuncSetAttribute(gemm_fw<256, 1>, cudaFuncAttributeMaxDynamicSharedMemorySize, SM_FW256);
    cudaFuncSetAttribute(gemm_fw<256, 0>, cudaFuncAttributeMaxDynamicSharedMemorySize, SM_FW256);
    cudaFuncSetAttribute(gemm_fw<64, 1>,  cudaFuncAttributeMaxDynamicSharedMemorySize, SM_FW64);
    cudaFuncSetAttribute(mma_gemm<64, 256>, cudaFuncAttributeMaxDynamicSharedMemorySize, SM_DOWN);

    const int GFW = E_EDGES / 128;   // 1024 CTAs

    // 0: round x
    round_copy_kernel<<<1024, 256>>>((const float4*)x, (float4*)xr, E_EDGES * H_DIM / 4);

    // 1: round all weights (single launch)
    WSet ws;
    const float* srcs[11] = {W_ji, W_kj, Wb1_1, Wb1_2, W_lin, Wa1_1, Wa1_2, Wa2_1, Wa2_2, W_down, W_up};
    const int offs[11]    = {WO_JI, WO_KJ, WO_B11, WO_B12, WO_LIN, WO_A11, WO_A12, WO_A21, WO_A22, WO_DOWN, WO_UP};
    const int n4s[11]     = {16384, 16384, 16384, 16384, 16384, 16384, 16384, 16384, 16384, 4096, 4096};
    for (int i = 0; i < 11; i++) { ws.src[i] = srcs[i]; ws.dst[i] = wr + offs[i]; ws.n4[i] = n4s[i]; }
    round_w_kernel<<<dim3(16, 11), 256>>>(ws);

    // 2: x_ji = silu(x@W_ji + b)            <- big GEMM at profile-reachable slots
    gemm_fw<256, 1><<<GFW, 256, SM_FW256>>>(xr, wr + WO_JI, b_ji, nullptr, xji);
    // 3: x_kj = silu(x@W_kj + b)
    gemm_fw<256, 1><<<GFW, 256, SM_FW256>>>(xr, wr + WO_KJ, b_kj, nullptr, bufA);
    // 4: gate
    rbf_gate_kernel<<<2048, 256>>>(bufA, rbf, W_rbf1, W_rbf2);
    // 5: x_kj_down = silu((x_kj*g) @ W_down)
    mma_gemm<64, 256><<<dim3(GFW, 1), 256, SM_DOWN>>>(bufA, wr + WO_DOWN, nullptr, nullptr, xkjd, I_DIM);
    // 6: zero agg
    zero_kernel<<<1024, 256>>>((float4*)agg, E_EDGES * I_DIM / 4);
    // 7: triplet message passing
    triplet_kernel<<<2048, 256>>>(sbf, idx_kj, idx_ji, W_sbf1, W_sbf2, xkjd, agg);
    // 8: h = x_ji + silu(agg @ W_up)
    gemm_fw<64, 1><<<GFW, 256, SM_FW64>>>(agg, wr + WO_UP, nullptr, xji, bufA);
    // 9-10: pre-skip residual pair
    gemm_fw<256, 1><<<GFW, 256, SM_FW256>>>(bufA, wr + WO_B11, bb1_1, nullptr, bufB);
    gemm_fw<256, 1><<<GFW, 256, SM_FW256>>>(bufB, wr + WO_B12, bb1_2, bufA, bufA);
    // 11: skip: h = silu(h@W_lin+b) + x
    gemm_fw<256, 1><<<GFW, 256, SM_FW256>>>(bufA, wr + WO_LIN, b_lin, x, bufB);
    // 12-13: post-skip residual pair 1
    gemm_fw<256, 1><<<GFW, 256, SM_FW256>>>(bufB, wr + WO_A11, ba1_1, nullptr, bufA);
    gemm_fw<256, 1><<<GFW, 256, SM_FW256>>>(bufA, wr + WO_A12, ba1_2, bufB, bufB);
    // 14-15: post-skip residual pair 2 -> final output (unrounded)
    gemm_fw<256, 1><<<GFW, 256, SM_FW256>>>(bufB, wr + WO_A21, ba2_1, nullptr, bufA);
    gemm_fw<256, 0><<<GFW, 256, SM_FW256>>>(bufA, wr + WO_A22, ba2_2, bufB, out);
}

// round 8
// speedup vs baseline: 1.4030x; 1.4030x over previous
#include <cuda_runtime.h>
#include <cstdint>
#include <cstddef>

// ---------------- problem constants ----------------
static constexpr int E_EDGES = 131072;
static constexpr int T_TRIP  = 1048576;
static constexpr int H_DIM   = 256;
static constexpr int I_DIM   = 64;
static constexpr int NR      = 6;
static constexpr int NSR     = 42;
static constexpr int BAS     = 8;

// ---------------- scratch (static device memory) ----------------
__device__ float g_xr  [(size_t)E_EDGES * H_DIM];
__device__ float g_xji [(size_t)E_EDGES * H_DIM];
__device__ float g_bufA[(size_t)E_EDGES * H_DIM];
__device__ float g_bufB[(size_t)E_EDGES * H_DIM];
__device__ float g_xkjd[(size_t)E_EDGES * I_DIM];
__device__ float g_agg [(size_t)E_EDGES * I_DIM];
__device__ float g_wr  [622592];   // tf32-rounded weights, concatenated

// weight offsets inside g_wr
static constexpr int WO_JI   = 0;
static constexpr int WO_KJ   = 65536;
static constexpr int WO_B11  = 131072;
static constexpr int WO_B12  = 196608;
static constexpr int WO_LIN  = 262144;
static constexpr int WO_A11  = 327680;
static constexpr int WO_A12  = 393216;
static constexpr int WO_A21  = 458752;
static constexpr int WO_A22  = 524288;
static constexpr int WO_DOWN = 589824;   // 256*64
static constexpr int WO_UP   = 606208;   // 64*256

// ---------------- helpers ----------------
__device__ __forceinline__ uint32_t smem_to_u32(const void* p) {
    uint32_t a;
    asm("{ .reg .u64 t; cvta.to.shared.u64 t, %1; cvt.u32.u64 %0, t; }" : "=r"(a) : "l"(p));
    return a;
}
__device__ __forceinline__ uint32_t tf32r(float v) {
    uint32_t o; asm("cvt.rna.tf32.f32 %0, %1;" : "=r"(o) : "f"(v)); return o;
}
__device__ __forceinline__ float silu_f(float v) {
    return v * (1.0f / (1.0f + __expf(-v)));
}
__device__ __forceinline__ void cp_async16(uint32_t dst, const void* src) {
    asm volatile("cp.async.cg.shared.global [%0], [%1], 16;" :: "r"(dst), "l"(src));
}
__device__ __forceinline__ void mma_tf32(float d[4], const uint32_t a[4], const uint32_t b[2]) {
    asm volatile(
        "mma.sync.aligned.m16n8k8.row.col.f32.tf32.tf32.f32 "
        "{%0,%1,%2,%3}, {%4,%5,%6,%7}, {%8,%9}, {%0,%1,%2,%3};"
        : "+f"(d[0]), "+f"(d[1]), "+f"(d[2]), "+f"(d[3])
        : "r"(a[0]), "r"(a[1]), "r"(a[2]), "r"(a[3]), "r"(b[0]), "r"(b[1]));
}

// ============ mma.sync tf32 GEMM: C = [res +] silu(A @ W [+ bias]) ============
// Block tile 128 x BN x 16; 8 warps (4M x 2N); warp tile 32 x BN/2; occ 2.
// Grid: x = N-tile (fast), y = M-tile  -> CTAs sharing an A-tile are adjacent (L2 reuse).
// B SMEM stride = BN + 8  ->  B-fragment LDS bank-conflict-free (8q+g covers 0..31).
template <int BN, int K>
__global__ void __launch_bounds__(256, 2)
mma_gemm(const float* __restrict__ A, const float* __restrict__ W,
         const float* __restrict__ bias, const float* __restrict__ res,
         float* __restrict__ C, int Nfull)
{
    constexpr int BM = 128, BK = 16, DEPTH = 3;
    constexpr int KT = K / BK;
    constexpr int AS_STRIDE = BK + 4;                 // 20: A-frags conflict-free
    constexpr int AS_STAGE  = BM * AS_STRIDE;
    constexpr int BS_STRIDE = BN + 8;                 // 136/72: B-frags conflict-free
    constexpr int BS_STAGE  = BK * BS_STRIDE;
    constexpr int NF = BN / 16;

    extern __shared__ float smf[];
    float* As = smf;
    float* Bs = smf + DEPTH * AS_STAGE;
    const uint32_t smemA = smem_to_u32(As);
    const uint32_t smemB = smem_to_u32(Bs);

    const int tid = threadIdx.x, lane = tid & 31, wid = tid >> 5;
    const int warpM = wid >> 1, warpN = wid & 1;
    const int row0 = blockIdx.y * BM;        // M-tile on y (slow axis)
    const int col0 = blockIdx.x * BN;        // N-tile on x (fast axis)
    const int g = lane >> 2, q = lane & 3;

    float acc[2][NF][4];
#pragma unroll
    for (int mf = 0; mf < 2; mf++)
#pragma unroll
        for (int nf = 0; nf < NF; nf++)
#pragma unroll
            for (int v = 0; v < 4; v++) acc[mf][nf][v] = 0.0f;

    auto load_stage = [&](int s, int kt) {
        const int k0 = kt * BK;
#pragma unroll
        for (int i = 0; i < 2; i++) {
            int id = tid + i * 256;
            int m = id >> 2, c4 = (id & 3) * 4;
            cp_async16(smemA + (uint32_t)(s * AS_STAGE + m * AS_STRIDE + c4) * 4,
                       A + (size_t)(row0 + m) * K + k0 + c4);
        }
        constexpr int BCH = BK * BN / 4;
#pragma unroll
        for (int i = 0; i < (BCH + 255) / 256; i++) {
            int id = tid + i * 256;
            if (id < BCH) {
                int k = id / (BN / 4), n4 = (id % (BN / 4)) * 4;
                cp_async16(smemB + (uint32_t)(s * BS_STAGE + k * BS_STRIDE + n4) * 4,
                           W + (size_t)(k0 + k) * Nfull + col0 + n4);
            }
        }
    };

#pragma unroll
    for (int s = 0; s < DEPTH - 1; s++) {
        load_stage(s, s);
        asm volatile("cp.async.commit_group;" ::: "memory");
    }

    for (int it = 0; it < KT; it++) {
        asm volatile("cp.async.wait_group %0;" :: "n"(DEPTH - 2) : "memory");
        __syncthreads();
        const int nx = it + DEPTH - 1;
        if (nx < KT) load_stage(nx % DEPTH, nx);
        asm volatile("cp.async.commit_group;" ::: "memory");

        const int s = it % DEPTH;
        const float* Asb = As + s * AS_STAGE;
        const float* Bsb = Bs + s * BS_STAGE;
#pragma unroll
        for (int ks = 0; ks < 2; ks++) {
            uint32_t af[2][4];
            uint32_t bf[NF][2];
#pragma unroll
            for (int mf = 0; mf < 2; mf++) {
                int r = warpM * 32 + mf * 16 + g;
                af[mf][0] = __float_as_uint(Asb[r * AS_STRIDE + ks * 8 + q]);
                af[mf][1] = __float_as_uint(Asb[(r + 8) * AS_STRIDE + ks * 8 + q]);
                af[mf][2] = __float_as_uint(Asb[r * AS_STRIDE + ks * 8 + q + 4]);
                af[mf][3] = __float_as_uint(Asb[(r + 8) * AS_STRIDE + ks * 8 + q + 4]);
            }
#pragma unroll
            for (int nf = 0; nf < NF; nf++) {
                int c = warpN * (BN / 2) + nf * 8 + g;
                bf[nf][0] = __float_as_uint(Bsb[(ks * 8 + q) * BS_STRIDE + c]);
                bf[nf][1] = __float_as_uint(Bsb[(ks * 8 + q + 4) * BS_STRIDE + c]);
            }
#pragma unroll
            for (int mf = 0; mf < 2; mf++)
#pragma unroll
                for (int nf = 0; nf < NF; nf++)
                    mma_tf32(acc[mf][nf], af[mf], bf[nf]);
        }
    }

    // epilogue: bias -> silu -> +res -> store (tf32-rounded unless ROUND off via res==C trick not needed)
#pragma unroll
    for (int mf = 0; mf < 2; mf++) {
#pragma unroll
        for (int nf = 0; nf < NF; nf++) {
            const int col = col0 + warpN * (BN / 2) + nf * 8 + 2 * q;
            float bv0 = 0.0f, bv1 = 0.0f;
            if (bias) { bv0 = bias[col]; bv1 = bias[col + 1]; }
#pragma unroll
            for (int h = 0; h < 2; h++) {
                const int row = row0 + warpM * 32 + mf * 16 + g + h * 8;
                float v0 = silu_f(acc[mf][nf][h * 2 + 0] + bv0);
                float v1 = silu_f(acc[mf][nf][h * 2 + 1] + bv1);
                const size_t off = (size_t)row * Nfull + col;
                if (res) {
                    float2 r = *reinterpret_cast<const float2*>(res + off);
                    v0 += r.x; v1 += r.y;
                }
                uint2 o;
                o.x = tf32r(v0);
                o.y = tf32r(v1);
                *reinterpret_cast<uint2*>(C + off) = o;
            }
        }
    }
}

static constexpr int mma_smem(int BN) {
    return 3 * (128 * 20 + 16 * (BN + 8)) * 4;
}

// ---------------- round x to tf32-representable fp32 ----------------
__global__ void round_copy_kernel(const float4* __restrict__ in, float4* __restrict__ out, int n4)
{
    int i = blockIdx.x * blockDim.x + threadIdx.x;
    int stride = gridDim.x * blockDim.x;
    for (; i < n4; i += stride) {
        float4 v = in[i];
        uint4 o;
        o.x = tf32r(v.x); o.y = tf32r(v.y); o.z = tf32r(v.z); o.w = tf32r(v.w);
        *reinterpret_cast<uint4*>(&out[i]) = o;
    }
}

// ---------------- round all weights, one launch ----------------
struct WSet { const float* src[11]; float* dst[11]; int n4[11]; };
__global__ void round_w_kernel(WSet ws)
{
    int seg = blockIdx.y;
    const float4* s = reinterpret_cast<const float4*>(ws.src[seg]);
    float4* d = reinterpret_cast<float4*>(ws.dst[seg]);
    int n4 = ws.n4[seg];
    for (int i = blockIdx.x * blockDim.x + threadIdx.x; i < n4; i += gridDim.x * blockDim.x) {
        float4 v = s[i];
        uint4 o;
        o.x = tf32r(v.x); o.y = tf32r(v.y); o.z = tf32r(v.z); o.w = tf32r(v.w);
        *reinterpret_cast<uint4*>(&d[i]) = o;
    }
}

// ---------------- rbf gating: xkj[r,:] *= (rbf[r,:] @ W1) @ W2 ; tf32-rounded ----------------
__global__ void rbf_gate_kernel(float* __restrict__ xkj,
                                const float* __restrict__ rbf,
                                const float* __restrict__ W1,   // [6,8]
                                const float* __restrict__ W2)   // [8,256]
{
    __shared__ __align__(16) float sW2[BAS * H_DIM];
    __shared__ float sW1[NR * BAS];
    for (int i = threadIdx.x; i < BAS * H_DIM; i += blockDim.x) sW2[i] = W2[i];
    for (int i = threadIdx.x; i < NR * BAS; i += blockDim.x)    sW1[i] = W1[i];
    __syncthreads();

    const int lane  = threadIdx.x & 31;
    const int wglob = (blockIdx.x * blockDim.x + threadIdx.x) >> 5;
    const int nwarp = (gridDim.x * blockDim.x) >> 5;
    const int j = lane & 7;
    const int g = lane >> 3;

    for (int r = wglob; r < E_EDGES; r += nwarp) {
        float s = 0.f;
        for (int i = g; i < NR; i += 4) s += rbf[(size_t)r * NR + i] * sW1[i * BAS + j];
        s += __shfl_xor_sync(0xffffffffu, s, 8);
        s += __shfl_xor_sync(0xffffffffu, s, 16);
        int c = lane * 8;
        float4 g0 = make_float4(0, 0, 0, 0), g1 = make_float4(0, 0, 0, 0);
#pragma unroll
        for (int jj = 0; jj < BAS; jj++) {
            float sj = __shfl_sync(0xffffffffu, s, jj);
            float4 w0 = *reinterpret_cast<const float4*>(&sW2[jj * H_DIM + c]);
            float4 w1 = *reinterpret_cast<const float4*>(&sW2[jj * H_DIM + c + 4]);
            g0.x += sj * w0.x; g0.y += sj * w0.y; g0.z += sj * w0.z; g0.w += sj * w0.w;
            g1.x += sj * w1.x; g1.y += sj * w1.y; g1.z += sj * w1.z; g1.w += sj * w1.w;
        }
        float4* p0 = reinterpret_cast<float4*>(&xkj[(size_t)r * H_DIM + c]);
        float4* p1 = reinterpret_cast<float4*>(&xkj[(size_t)r * H_DIM + c + 4]);
        float4 x0 = *p0, x1 = *p1;
        uint4 o0, o1;
        o0.x = tf32r(x0.x * g0.x); o0.y = tf32r(x0.y * g0.y);
        o0.z = tf32r(x0.z * g0.z); o0.w = tf32r(x0.w * g0.w);
        o1.x = tf32r(x1.x * g1.x); o1.y = tf32r(x1.y * g1.y);
        o1.z = tf32r(x1.z * g1.z); o1.w = tf32r(x1.w * g1.w);
        *reinterpret_cast<uint4*>(p0) = o0;
        *reinterpret_cast<uint4*>(p1) = o1;
    }
}

// ---------------- zero scratch ----------------
__global__ void zero_kernel(float4* __restrict__ p, int n4)
{
    int i = blockIdx.x * blockDim.x + threadIdx.x;
    int stride = gridDim.x * blockDim.x;
    for (; i < n4; i += stride) p[i] = make_float4(0, 0, 0, 0);
}

// ---------------- triplet pass ----------------
__global__ void triplet_kernel(const float* __restrict__ sbf,
                               const int* __restrict__ idx_kj,
                               const int* __restrict__ idx_ji,
                               const float* __restrict__ W1,   // [42,8]
                               const float* __restrict__ W2,   // [8,64]
                               const float* __restrict__ xkjd, // [E,64]
                               float* __restrict__ agg)        // [E,64]
{
    __shared__ float sW1[NSR * BAS];
    __shared__ __align__(16) float sW2[BAS * I_DIM];
    for (int i = threadIdx.x; i < NSR * BAS; i += blockDim.x) sW1[i] = W1[i];
    for (int i = threadIdx.x; i < BAS * I_DIM; i += blockDim.x) sW2[i] = W2[i];
    __syncthreads();

    const int lane  = threadIdx.x & 31;
    const int wglob = (blockIdx.x * blockDim.x + threadIdx.x) >> 5;
    const int nwarp = (gridDim.x * blockDim.x) >> 5;
    const int sub = lane >> 4;
    const int sl  = lane & 15;
    const int j   = sl & 7;
    const int g   = sl >> 3;

    for (int p = wglob; p * 2 < T_TRIP; p += nwarp) {
        int t = p * 2 + sub;
        const float* srow = sbf + (size_t)t * NSR;
        float s = 0.f;
        for (int i = g; i < NSR; i += 2) s += srow[i] * sW1[i * BAS + j];
        s += __shfl_xor_sync(0xffffffffu, s, 8);

        int ekj = idx_kj[t];
        int eji = idx_ji[t];
        int c = sl * 4;
        float4 xv = *reinterpret_cast<const float4*>(&xkjd[(size_t)ekj * I_DIM + c]);
        float4 m = make_float4(0, 0, 0, 0);
#pragma unroll
        for (int jj = 0; jj < BAS; jj++) {
            float sj = __shfl_sync(0xffffffffu, s, (sub << 4) + jj);
            float4 w = *reinterpret_cast<const float4*>(&sW2[jj * I_DIM + c]);
            m.x += sj * w.x; m.y += sj * w.y; m.z += sj * w.z; m.w += sj * w.w;
        }
        m.x *= xv.x; m.y *= xv.y; m.z *= xv.z; m.w *= xv.w;
        atomicAdd(reinterpret_cast<float4*>(&agg[(size_t)eji * I_DIM + c]), m);
    }
}

// ---------------- launch ----------------
extern "C" void kernel_launch(void* const* d_in, const int* in_sizes, int n_in,
                              void* d_out, int out_size)
{
    const float* x      = (const float*)d_in[0];
    const float* rbf    = (const float*)d_in[1];
    const float* sbf    = (const float*)d_in[2];
    const int*   idx_kj = (const int*)d_in[3];
    const int*   idx_ji = (const int*)d_in[4];
    const float* W_ji   = (const float*)d_in[5];
    const float* b_ji   = (const float*)d_in[6];
    const float* W_kj   = (const float*)d_in[7];
    const float* b_kj   = (const float*)d_in[8];
    const float* W_rbf1 = (const float*)d_in[9];
    const float* W_rbf2 = (const float*)d_in[10];
    const float* W_sbf1 = (const float*)d_in[11];
    const float* W_sbf2 = (const float*)d_in[12];
    const float* W_down = (const float*)d_in[13];
    const float* W_up   = (const float*)d_in[14];
    const float* Wb1_1  = (const float*)d_in[15];
    const float* bb1_1  = (const float*)d_in[16];
    const float* Wb1_2  = (const float*)d_in[17];
    const float* bb1_2  = (const float*)d_in[18];
    const float* W_lin  = (const float*)d_in[19];
    const float* b_lin  = (const float*)d_in[20];
    const float* Wa1_1  = (const float*)d_in[21];
    const float* ba1_1  = (const float*)d_in[22];
    const float* Wa1_2  = (const float*)d_in[23];
    const float* ba1_2  = (const float*)d_in[24];
    const float* Wa2_1  = (const float*)d_in[25];
    const float* ba2_1  = (const float*)d_in[26];
    const float* Wa2_2  = (const float*)d_in[27];
    const float* ba2_2  = (const float*)d_in[28];
    float* out = (float*)d_out;

    float *xr, *xji, *bufA, *bufB, *xkjd, *agg, *wr;
    cudaGetSymbolAddress((void**)&xr,   g_xr);
    cudaGetSymbolAddress((void**)&xji,  g_xji);
    cudaGetSymbolAddress((void**)&bufA, g_bufA);
    cudaGetSymbolAddress((void**)&bufB, g_bufB);
    cudaGetSymbolAddress((void**)&xkjd, g_xkjd);
    cudaGetSymbolAddress((void**)&agg,  g_agg);
    cudaGetSymbolAddress((void**)&wr,   g_wr);

    constexpr int SM_BIG  = mma_smem(128);   // 56,832 B -> occ 2
    constexpr int SM_DOWN = mma_smem(64);
    cudaFuncSetAttribute(mma_gemm<128, 256>, cudaFuncAttributeMaxDynamicSharedMemorySize, SM_BIG);
    cudaFuncSetAttribute(mma_gemm<64, 256>,  cudaFuncAttributeMaxDynamicSharedMemorySize, SM_DOWN);
    cudaFuncSetAttribute(mma_gemm<128, 64>,  cudaFuncAttributeMaxDynamicSharedMemorySize, SM_BIG);

    const dim3 gBig(2, E_EDGES / 128);   // x = N-tile (fast) -> A-tile L2 reuse
    const dim3 gDown(1, E_EDGES / 128);

    // 0: round x
    round_copy_kernel<<<1024, 256>>>((const float4*)x, (float4*)xr, E_EDGES * H_DIM / 4);

    // 1: round all weights (single launch)
    WSet ws;
    const float* srcs[11] = {W_ji, W_kj, Wb1_1, Wb1_2, W_lin, Wa1_1, Wa1_2, Wa2_1, Wa2_2, W_down, W_up};
    const int offs[11]    = {WO_JI, WO_KJ, WO_B11, WO_B12, WO_LIN, WO_A11, WO_A12, WO_A21, WO_A22, WO_DOWN, WO_UP};
    const int n4s[11]     = {16384, 16384, 16384, 16384, 16384, 16384, 16384, 16384, 16384, 4096, 4096};
    for (int i = 0; i < 11; i++) { ws.src[i] = srcs[i]; ws.dst[i] = wr + offs[i]; ws.n4[i] = n4s[i]; }
    round_w_kernel<<<dim3(16, 11), 256>>>(ws);

    // 2: x_ji = silu(x@W_ji + b)
    mma_gemm<128, 256><<<gBig, 256, SM_BIG>>>(xr, wr + WO_JI, b_ji, nullptr, xji, H_DIM);
    // 3: x_kj = silu(x@W_kj + b)
    mma_gemm<128, 256><<<gBig, 256, SM_BIG>>>(xr, wr + WO_KJ, b_kj, nullptr, bufA, H_DIM);
    // 4: gate
    rbf_gate_kernel<<<2048, 256>>>(bufA, rbf, W_rbf1, W_rbf2);
    // 5: x_kj_down = silu((x_kj*g) @ W_down)
    mma_gemm<64, 256><<<gDown, 256, SM_DOWN>>>(bufA, wr + WO_DOWN, nullptr, nullptr, xkjd, I_DIM);
    // 6: zero agg
    zero_kernel<<<1024, 256>>>((float4*)agg, E_EDGES * I_DIM / 4);
    // 7: triplet message passing
    triplet_kernel<<<2048, 256>>>(sbf, idx_kj, idx_ji, W_sbf1, W_sbf2, xkjd, agg);
    // 8: h = x_ji + silu(agg @ W_up)
    mma_gemm<128, 64><<<gBig, 256, SM_BIG>>>(agg, wr + WO_UP, nullptr, xji, bufA, H_DIM);
    // 9-10: pre-skip residual pair
    mma_gemm<128, 256><<<gBig, 256, SM_BIG>>>(bufA, wr + WO_B11, bb1_1, nullptr, bufB, H_DIM);
    mma_gemm<128, 256><<<gBig, 256, SM_BIG>>>(bufB, wr + WO_B12, bb1_2, bufA, bufA, H_DIM);
    // 11: skip: h = silu(h@W_lin+b) + x
    mma_gemm<128, 256><<<gBig, 256, SM_BIG>>>(bufA, wr + WO_LIN, b_lin, x, bufB, H_DIM);
    // 12-13: post-skip residual pair 1
    mma_gemm<128, 256><<<gBig, 256, SM_BIG>>>(bufB, wr + WO_A11, ba1_1, nullptr, bufA, H_DIM);
    mma_gemm<128, 256><<<gBig, 256, SM_BIG>>>(bufA, wr + WO_A12, ba1_2, bufB, bufB, H_DIM);
    // 14-15: post-skip residual pair 2 -> final output
    mma_gemm<128, 256><<<gBig, 256, SM_BIG>>>(bufB, wr + WO_A21, ba2_1, nullptr, bufA, H_DIM);
    mma_gemm<128, 256><<<gBig, 256, SM_BIG>>>(bufA, wr + WO_A22, ba2_2, bufB, out, H_DIM);
}

// round 9
// speedup vs baseline: 1.4677x; 1.0461x over previous
#include <cuda_runtime.h>
#include <cstdint>
#include <cstddef>

// ---------------- problem constants ----------------
static constexpr int E_EDGES = 131072;
static constexpr int T_TRIP  = 1048576;
static constexpr int H_DIM   = 256;
static constexpr int I_DIM   = 64;
static constexpr int NR      = 6;
static constexpr int NSR     = 42;
static constexpr int BAS     = 8;

// ---------------- scratch (static device memory) ----------------
__device__ float g_xr  [(size_t)E_EDGES * H_DIM];
__device__ float g_xji [(size_t)E_EDGES * H_DIM];
__device__ float g_bufA[(size_t)E_EDGES * H_DIM];
__device__ float g_bufB[(size_t)E_EDGES * H_DIM];
__device__ float g_xkjd[(size_t)E_EDGES * I_DIM];
__device__ float g_agg [(size_t)E_EDGES * I_DIM];
__device__ float g_wr  [622592];   // tf32-rounded weights, concatenated

// weight offsets inside g_wr
static constexpr int WO_JI   = 0;
static constexpr int WO_KJ   = 65536;
static constexpr int WO_B11  = 131072;
static constexpr int WO_B12  = 196608;
static constexpr int WO_LIN  = 262144;
static constexpr int WO_A11  = 327680;
static constexpr int WO_A12  = 393216;
static constexpr int WO_A21  = 458752;
static constexpr int WO_A22  = 524288;
static constexpr int WO_DOWN = 589824;   // 256*64
static constexpr int WO_UP   = 606208;   // 64*256

// ---------------- helpers ----------------
__device__ __forceinline__ uint32_t smem_to_u32(const void* p) {
    uint32_t a;
    asm("{ .reg .u64 t; cvta.to.shared.u64 t, %1; cvt.u32.u64 %0, t; }" : "=r"(a) : "l"(p));
    return a;
}
__device__ __forceinline__ uint32_t tf32r(float v) {
    uint32_t o; asm("cvt.rna.tf32.f32 %0, %1;" : "=r"(o) : "f"(v)); return o;
}
__device__ __forceinline__ float silu_f(float v) {
    return v * (1.0f / (1.0f + __expf(-v)));
}
__device__ __forceinline__ void cp_async16(uint32_t dst, const void* src) {
    asm volatile("cp.async.cg.shared.global [%0], [%1], 16;" :: "r"(dst), "l"(src));
}
__device__ __forceinline__ void mma_tf32(float d[4], const uint32_t a[4], const uint32_t b[2]) {
    asm volatile(
        "mma.sync.aligned.m16n8k8.row.col.f32.tf32.tf32.f32 "
        "{%0,%1,%2,%3}, {%4,%5,%6,%7}, {%8,%9}, {%0,%1,%2,%3};"
        : "+f"(d[0]), "+f"(d[1]), "+f"(d[2]), "+f"(d[3])
        : "r"(a[0]), "r"(a[1]), "r"(a[2]), "r"(a[3]), "r"(b[0]), "r"(b[1]));
}

// ============ mma.sync tf32 GEMM: C = [res +] silu(A @ W [+ bias]) ============
// Block tile 128 x BN x 32; 8 warps (4M x 2N); warp tile 32 x BN/2; occ 2.
// BK=32, DEPTH=3: 8 barriers per K=256 (vs 16), 4 unrolled k-slabs per barrier
// for LDS/MMA interleave. B SMEM stride = BN + 8 (conflict-free B-frags);
// A stride 36 (conflict-free A-frags: bank = 4g+q unique per lane).
template <int BN, int K>
__global__ void __launch_bounds__(256, 2)
mma_gemm(const float* __restrict__ A, const float* __restrict__ W,
         const float* __restrict__ bias, const float* __restrict__ res,
         float* __restrict__ C, int Nfull)
{
    constexpr int BM = 128, BK = 32, DEPTH = 3;
    constexpr int KT = K / BK;
    constexpr int AS_STRIDE = BK + 4;                 // 36
    constexpr int AS_STAGE  = BM * AS_STRIDE;         // 4608 floats
    constexpr int BS_STRIDE = BN + 8;                 // 136 / 72
    constexpr int BS_STAGE  = BK * BS_STRIDE;
    constexpr int NF = BN / 16;

    extern __shared__ float smf[];
    float* As = smf;
    float* Bs = smf + DEPTH * AS_STAGE;
    const uint32_t smemA = smem_to_u32(As);
    const uint32_t smemB = smem_to_u32(Bs);

    const int tid = threadIdx.x, lane = tid & 31, wid = tid >> 5;
    const int warpM = wid >> 1, warpN = wid & 1;
    const int row0 = blockIdx.y * BM;        // M-tile on y (slow axis)
    const int col0 = blockIdx.x * BN;        // N-tile on x (fast axis) -> A-tile L2 reuse
    const int g = lane >> 2, q = lane & 3;

    float acc[2][NF][4];
#pragma unroll
    for (int mf = 0; mf < 2; mf++)
#pragma unroll
        for (int nf = 0; nf < NF; nf++)
#pragma unroll
            for (int v = 0; v < 4; v++) acc[mf][nf][v] = 0.0f;

    auto load_stage = [&](int s, int kt) {
        const int k0 = kt * BK;
        // A: 128 x 32 floats = 1024 16B chunks, 4 per thread
#pragma unroll
        for (int i = 0; i < 4; i++) {
            int id = tid + i * 256;
            int m = id >> 3, c4 = (id & 7) * 4;
            cp_async16(smemA + (uint32_t)(s * AS_STAGE + m * AS_STRIDE + c4) * 4,
                       A + (size_t)(row0 + m) * K + k0 + c4);
        }
        // B: 32 x BN floats = (32*BN/4) chunks
        constexpr int BCH = BK * BN / 4;
#pragma unroll
        for (int i = 0; i < BCH / 256; i++) {
            int id = tid + i * 256;
            int k = id / (BN / 4), n4 = (id % (BN / 4)) * 4;
            cp_async16(smemB + (uint32_t)(s * BS_STAGE + k * BS_STRIDE + n4) * 4,
                       W + (size_t)(k0 + k) * Nfull + col0 + n4);
        }
    };

#pragma unroll
    for (int s = 0; s < DEPTH - 1; s++) {
        if (s < KT) load_stage(s, s);
        asm volatile("cp.async.commit_group;" ::: "memory");
    }

    for (int it = 0; it < KT; it++) {
        asm volatile("cp.async.wait_group %0;" :: "n"(DEPTH - 2) : "memory");
        __syncthreads();
        const int nx = it + DEPTH - 1;
        if (nx < KT) load_stage(nx % DEPTH, nx);
        asm volatile("cp.async.commit_group;" ::: "memory");

        const int s = it % DEPTH;
        const float* Asb = As + s * AS_STAGE;
        const float* Bsb = Bs + s * BS_STAGE;
#pragma unroll
        for (int ks = 0; ks < 4; ks++) {
            uint32_t af[2][4];
            uint32_t bf[NF][2];
#pragma unroll
            for (int mf = 0; mf < 2; mf++) {
                int r = warpM * 32 + mf * 16 + g;
                af[mf][0] = __float_as_uint(Asb[r * AS_STRIDE + ks * 8 + q]);
                af[mf][1] = __float_as_uint(Asb[(r + 8) * AS_STRIDE + ks * 8 + q]);
                af[mf][2] = __float_as_uint(Asb[r * AS_STRIDE + ks * 8 + q + 4]);
                af[mf][3] = __float_as_uint(Asb[(r + 8) * AS_STRIDE + ks * 8 + q + 4]);
            }
#pragma unroll
            for (int nf = 0; nf < NF; nf++) {
                int c = warpN * (BN / 2) + nf * 8 + g;
                bf[nf][0] = __float_as_uint(Bsb[(ks * 8 + q) * BS_STRIDE + c]);
                bf[nf][1] = __float_as_uint(Bsb[(ks * 8 + q + 4) * BS_STRIDE + c]);
            }
#pragma unroll
            for (int mf = 0; mf < 2; mf++)
#pragma unroll
                for (int nf = 0; nf < NF; nf++)
                    mma_tf32(acc[mf][nf], af[mf], bf[nf]);
        }
    }

    // epilogue: bias -> silu -> +res -> tf32-rounded store
#pragma unroll
    for (int mf = 0; mf < 2; mf++) {
#pragma unroll
        for (int nf = 0; nf < NF; nf++) {
            const int col = col0 + warpN * (BN / 2) + nf * 8 + 2 * q;
            float bv0 = 0.0f, bv1 = 0.0f;
            if (bias) { bv0 = bias[col]; bv1 = bias[col + 1]; }
#pragma unroll
            for (int h = 0; h < 2; h++) {
                const int row = row0 + warpM * 32 + mf * 16 + g + h * 8;
                float v0 = silu_f(acc[mf][nf][h * 2 + 0] + bv0);
                float v1 = silu_f(acc[mf][nf][h * 2 + 1] + bv1);
                const size_t off = (size_t)row * Nfull + col;
                if (res) {
                    float2 r = *reinterpret_cast<const float2*>(res + off);
                    v0 += r.x; v1 += r.y;
                }
                uint2 o;
                o.x = tf32r(v0);
                o.y = tf32r(v1);
                *reinterpret_cast<uint2*>(C + off) = o;
            }
        }
    }
}

static constexpr int mma_smem(int BN) {
    return 3 * (128 * 36 + 32 * (BN + 8)) * 4;
}

// ---------------- round x to tf32-representable fp32 ----------------
__global__ void round_copy_kernel(const float4* __restrict__ in, float4* __restrict__ out, int n4)
{
    int i = blockIdx.x * blockDim.x + threadIdx.x;
    int stride = gridDim.x * blockDim.x;
    for (; i < n4; i += stride) {
        float4 v = in[i];
        uint4 o;
        o.x = tf32r(v.x); o.y = tf32r(v.y); o.z = tf32r(v.z); o.w = tf32r(v.w);
        *reinterpret_cast<uint4*>(&out[i]) = o;
    }
}

// ---------------- round all weights, one launch ----------------
struct WSet { const float* src[11]; float* dst[11]; int n4[11]; };
__global__ void round_w_kernel(WSet ws)
{
    int seg = blockIdx.y;
    const float4* s = reinterpret_cast<const float4*>(ws.src[seg]);
    float4* d = reinterpret_cast<float4*>(ws.dst[seg]);
    int n4 = ws.n4[seg];
    for (int i = blockIdx.x * blockDim.x + threadIdx.x; i < n4; i += gridDim.x * blockDim.x) {
        float4 v = s[i];
        uint4 o;
        o.x = tf32r(v.x); o.y = tf32r(v.y); o.z = tf32r(v.z); o.w = tf32r(v.w);
        *reinterpret_cast<uint4*>(&d[i]) = o;
    }
}

// ---------------- rbf gating: xkj[r,:] *= (rbf[r,:] @ W1) @ W2 ; tf32-rounded ----------------
__global__ void rbf_gate_kernel(float* __restrict__ xkj,
                                const float* __restrict__ rbf,
                                const float* __restrict__ W1,   // [6,8]
                                const float* __restrict__ W2)   // [8,256]
{
    __shared__ __align__(16) float sW2[BAS * H_DIM];
    __shared__ float sW1[NR * BAS];
    for (int i = threadIdx.x; i < BAS * H_DIM; i += blockDim.x) sW2[i] = W2[i];
    for (int i = threadIdx.x; i < NR * BAS; i += blockDim.x)    sW1[i] = W1[i];
    __syncthreads();

    const int lane  = threadIdx.x & 31;
    const int wglob = (blockIdx.x * blockDim.x + threadIdx.x) >> 5;
    const int nwarp = (gridDim.x * blockDim.x) >> 5;
    const int j = lane & 7;
    const int g = lane >> 3;

    for (int r = wglob; r < E_EDGES; r += nwarp) {
        float s = 0.f;
        for (int i = g; i < NR; i += 4) s += rbf[(size_t)r * NR + i] * sW1[i * BAS + j];
        s += __shfl_xor_sync(0xffffffffu, s, 8);
        s += __shfl_xor_sync(0xffffffffu, s, 16);
        int c = lane * 8;
        float4 g0 = make_float4(0, 0, 0, 0), g1 = make_float4(0, 0, 0, 0);
#pragma unroll
        for (int jj = 0; jj < BAS; jj++) {
            float sj = __shfl_sync(0xffffffffu, s, jj);
            float4 w0 = *reinterpret_cast<const float4*>(&sW2[jj * H_DIM + c]);
            float4 w1 = *reinterpret_cast<const float4*>(&sW2[jj * H_DIM + c + 4]);
            g0.x += sj * w0.x; g0.y += sj * w0.y; g0.z += sj * w0.z; g0.w += sj * w0.w;
            g1.x += sj * w1.x; g1.y += sj * w1.y; g1.z += sj * w1.z; g1.w += sj * w1.w;
        }
        float4* p0 = reinterpret_cast<float4*>(&xkj[(size_t)r * H_DIM + c]);
        float4* p1 = reinterpret_cast<float4*>(&xkj[(size_t)r * H_DIM + c + 4]);
        float4 x0 = *p0, x1 = *p1;
        uint4 o0, o1;
        o0.x = tf32r(x0.x * g0.x); o0.y = tf32r(x0.y * g0.y);
        o0.z = tf32r(x0.z * g0.z); o0.w = tf32r(x0.w * g0.w);
        o1.x = tf32r(x1.x * g1.x); o1.y = tf32r(x1.y * g1.y);
        o1.z = tf32r(x1.z * g1.z); o1.w = tf32r(x1.w * g1.w);
        *reinterpret_cast<uint4*>(p0) = o0;
        *reinterpret_cast<uint4*>(p1) = o1;
    }
}

// ---------------- zero scratch ----------------
__global__ void zero_kernel(float4* __restrict__ p, int n4)
{
    int i = blockIdx.x * blockDim.x + threadIdx.x;
    int stride = gridDim.x * blockDim.x;
    for (; i < n4; i += stride) p[i] = make_float4(0, 0, 0, 0);
}

// ---------------- triplet pass ----------------
__global__ void triplet_kernel(const float* __restrict__ sbf,
                               const int* __restrict__ idx_kj,
                               const int* __restrict__ idx_ji,
                               const float* __restrict__ W1,   // [42,8]
                               const float* __restrict__ W2,   // [8,64]
                               const float* __restrict__ xkjd, // [E,64]
                               float* __restrict__ agg)        // [E,64]
{
    __shared__ float sW1[NSR * BAS];
    __shared__ __align__(16) float sW2[BAS * I_DIM];
    for (int i = threadIdx.x; i < NSR * BAS; i += blockDim.x) sW1[i] = W1[i];
    for (int i = threadIdx.x; i < BAS * I_DIM; i += blockDim.x) sW2[i] = W2[i];
    __syncthreads();

    const int lane  = threadIdx.x & 31;
    const int wglob = (blockIdx.x * blockDim.x + threadIdx.x) >> 5;
    const int nwarp = (gridDim.x * blockDim.x) >> 5;
    const int sub = lane >> 4;
    const int sl  = lane & 15;
    const int j   = sl & 7;
    const int g   = sl >> 3;

    for (int p = wglob; p * 2 < T_TRIP; p += nwarp) {
        int t = p * 2 + sub;
        const float* srow = sbf + (size_t)t * NSR;
        float s = 0.f;
        for (int i = g; i < NSR; i += 2) s += srow[i] * sW1[i * BAS + j];
        s += __shfl_xor_sync(0xffffffffu, s, 8);

        int ekj = idx_kj[t];
        int eji = idx_ji[t];
        int c = sl * 4;
        float4 xv = *reinterpret_cast<const float4*>(&xkjd[(size_t)ekj * I_DIM + c]);
        float4 m = make_float4(0, 0, 0, 0);
#pragma unroll
        for (int jj = 0; jj < BAS; jj++) {
            float sj = __shfl_sync(0xffffffffu, s, (sub << 4) + jj);
            float4 w = *reinterpret_cast<const float4*>(&sW2[jj * I_DIM + c]);
            m.x += sj * w.x; m.y += sj * w.y; m.z += sj * w.z; m.w += sj * w.w;
        }
        m.x *= xv.x; m.y *= xv.y; m.z *= xv.z; m.w *= xv.w;
        atomicAdd(reinterpret_cast<float4*>(&agg[(size_t)eji * I_DIM + c]), m);
    }
}

// ---------------- launch ----------------
extern "C" void kernel_launch(void* const* d_in, const int* in_sizes, int n_in,
                              void* d_out, int out_size)
{
    const float* x      = (const float*)d_in[0];
    const float* rbf    = (const float*)d_in[1];
    const float* sbf    = (const float*)d_in[2];
    const int*   idx_kj = (const int*)d_in[3];
    const int*   idx_ji = (const int*)d_in[4];
    const float* W_ji   = (const float*)d_in[5];
    const float* b_ji   = (const float*)d_in[6];
    const float* W_kj   = (const float*)d_in[7];
    const float* b_kj   = (const float*)d_in[8];
    const float* W_rbf1 = (const float*)d_in[9];
    const float* W_rbf2 = (const float*)d_in[10];
    const float* W_sbf1 = (const float*)d_in[11];
    const float* W_sbf2 = (const float*)d_in[12];
    const float* W_down = (const float*)d_in[13];
    const float* W_up   = (const float*)d_in[14];
    const float* Wb1_1  = (const float*)d_in[15];
    const float* bb1_1  = (const float*)d_in[16];
    const float* Wb1_2  = (const float*)d_in[17];
    const float* bb1_2  = (const float*)d_in[18];
    const float* W_lin  = (const float*)d_in[19];
    const float* b_lin  = (const float*)d_in[20];
    const float* Wa1_1  = (const float*)d_in[21];
    const float* ba1_1  = (const float*)d_in[22];
    const float* Wa1_2  = (const float*)d_in[23];
    const float* ba1_2  = (const float*)d_in[24];
    const float* Wa2_1  = (const float*)d_in[25];
    const float* ba2_1  = (const float*)d_in[26];
    const float* Wa2_2  = (const float*)d_in[27];
    const float* ba2_2  = (const float*)d_in[28];
    float* out = (float*)d_out;

    float *xr, *xji, *bufA, *bufB, *xkjd, *agg, *wr;
    cudaGetSymbolAddress((void**)&xr,   g_xr);
    cudaGetSymbolAddress((void**)&xji,  g_xji);
    cudaGetSymbolAddress((void**)&bufA, g_bufA);
    cudaGetSymbolAddress((void**)&bufB, g_bufB);
    cudaGetSymbolAddress((void**)&xkjd, g_xkjd);
    cudaGetSymbolAddress((void**)&agg,  g_agg);
    cudaGetSymbolAddress((void**)&wr,   g_wr);

    constexpr int SM_BIG  = mma_smem(128);   // 107,520 B -> occ 2 (215 KB/SM)
    constexpr int SM_DOWN = mma_smem(64);
    cudaFuncSetAttribute(mma_gemm<128, 256>, cudaFuncAttributeMaxDynamicSharedMemorySize, SM_BIG);
    cudaFuncSetAttribute(mma_gemm<64, 256>,  cudaFuncAttributeMaxDynamicSharedMemorySize, SM_DOWN);
    cudaFuncSetAttribute(mma_gemm<128, 64>,  cudaFuncAttributeMaxDynamicSharedMemorySize, SM_BIG);

    const dim3 gBig(2, E_EDGES / 128);   // x = N-tile (fast) -> A-tile L2 reuse
    const dim3 gDown(1, E_EDGES / 128);

    // 0: round x
    round_copy_kernel<<<1024, 256>>>((const float4*)x, (float4*)xr, E_EDGES * H_DIM / 4);

    // 1: round all weights (single launch)
    WSet ws;
    const float* srcs[11] = {W_ji, W_kj, Wb1_1, Wb1_2, W_lin, Wa1_1, Wa1_2, Wa2_1, Wa2_2, W_down, W_up};
    const int offs[11]    = {WO_JI, WO_KJ, WO_B11, WO_B12, WO_LIN, WO_A11, WO_A12, WO_A21, WO_A22, WO_DOWN, WO_UP};
    const int n4s[11]     = {16384, 16384, 16384, 16384, 16384, 16384, 16384, 16384, 16384, 4096, 4096};
    for (int i = 0; i < 11; i++) { ws.src[i] = srcs[i]; ws.dst[i] = wr + offs[i]; ws.n4[i] = n4s[i]; }
    round_w_kernel<<<dim3(16, 11), 256>>>(ws);

    // 2: x_ji = silu(x@W_ji + b)
    mma_gemm<128, 256><<<gBig, 256, SM_BIG>>>(xr, wr + WO_JI, b_ji, nullptr, xji, H_DIM);
    // 3: x_kj = silu(x@W_kj + b)
    mma_gemm<128, 256><<<gBig, 256, SM_BIG>>>(xr, wr + WO_KJ, b_kj, nullptr, bufA, H_DIM);
    // 4: gate
    rbf_gate_kernel<<<2048, 256>>>(bufA, rbf, W_rbf1, W_rbf2);
    // 5: x_kj_down = silu((x_kj*g) @ W_down)
    mma_gemm<64, 256><<<gDown, 256, SM_DOWN>>>(bufA, wr + WO_DOWN, nullptr, nullptr, xkjd, I_DIM);
    // 6: zero agg
    zero_kernel<<<1024, 256>>>((float4*)agg, E_EDGES * I_DIM / 4);
    // 7: triplet message passing
    triplet_kernel<<<2048, 256>>>(sbf, idx_kj, idx_ji, W_sbf1, W_sbf2, xkjd, agg);
    // 8: h = x_ji + silu(agg @ W_up)
    mma_gemm<128, 64><<<gBig, 256, SM_BIG>>>(agg, wr + WO_UP, nullptr, xji, bufA, H_DIM);
    // 9-10: pre-skip residual pair
    mma_gemm<128, 256><<<gBig, 256, SM_BIG>>>(bufA, wr + WO_B11, bb1_1, nullptr, bufB, H_DIM);
    mma_gemm<128, 256><<<gBig, 256, SM_BIG>>>(bufB, wr + WO_B12, bb1_2, bufA, bufA, H_DIM);
    // 11: skip: h = silu(h@W_lin+b) + x
    mma_gemm<128, 256><<<gBig, 256, SM_BIG>>>(bufA, wr + WO_LIN, b_lin, x, bufB, H_DIM);
    // 12-13: post-skip residual pair 1
    mma_gemm<128, 256><<<gBig, 256, SM_BIG>>>(bufB, wr + WO_A11, ba1_1, nullptr, bufA, H_DIM);
    mma_gemm<128, 256><<<gBig, 256, SM_BIG>>>(bufA, wr + WO_A12, ba1_2, bufB, bufB, H_DIM);
    // 14-15: post-skip residual pair 2 -> final output
    mma_gemm<128, 256><<<gBig, 256, SM_BIG>>>(bufB, wr + WO_A21, ba2_1, nullptr, bufA, H_DIM);
    mma_gemm<128, 256><<<gBig, 256, SM_BIG>>>(bufA, wr + WO_A22, ba2_2, bufB, out, H_DIM);
}